// round 10
// baseline (speedup 1.0000x reference)
#include <cuda_runtime.h>
#include <cuda_fp16.h>
#include <cstdint>

// Problem constants
#define BB   8
#define NN   4096
#define EE   16384
#define PP   64
#define DD   256
#define HH   512
#define MSGD 256
#define UPDD 254
#define STEPS 3
#define KDIM 512

// Tiling: CTA 128x128, 4 warps (2 row x 2 col), warp tile 64x64, BK=64 halves
// 2 CTAs/SM (regs<=256, smem ~99KB each) -> independent barrier domains.
#define TMv 128
#define TNv 128
#define BKh 64                        // k-halves per chunk (128 bytes)
#define NCHUNK (KDIM / BKh)           // 8
#define STAGES 3
#define ABYTES_ (TMv * 128)           // 16384
#define BBYTES_ (TNv * 128)           // 16384
#define BUFBYTES (ABYTES_ + BBYTES_)  // 32768
#define SOFF_SRC (STAGES * BUFBYTES)        // 98304
#define SOFF_SNK (SOFF_SRC + 512)
#define SMEM_BYTES (SOFF_SNK + 512)         // 99328

// ---------------------------------------------------------------------------
// Scratch (static device globals — no runtime allocation)
// ---------------------------------------------------------------------------
__device__ float  g_ns   [BB * NN * DD];           // fp32 node states
__device__ __half g_nstf [BB * NN * DD];           // fp16 shadow of ns
__device__ __half g_he   [(size_t)BB * EE * HH];   // fp16 edge hidden
__device__ float  g_inc  [BB * NN * MSGD];         // fp32 incoming (atomics)
__device__ __half g_inctf[BB * NN * MSGD];         // fp16 shadow
__device__ __half g_hn   [BB * NN * HH];           // fp16 node hidden
__device__ __half g_wte1[HH   * KDIM];
__device__ __half g_wte2[MSGD * KDIM];
__device__ __half g_wtn1[HH   * KDIM];
__device__ __half g_wtn2[UPDD * KDIM];

// ---------------------------------------------------------------------------
// Helpers (portable PTX only: cp.async + ldmatrix + mma.sync fp16)
// ---------------------------------------------------------------------------
__device__ __forceinline__ uint32_t smem_u32(const void* p) {
    uint32_t a;
    asm("{ .reg .u64 t; cvta.to.shared.u64 t, %1; cvt.u32.u64 %0, t; }" : "=r"(a) : "l"(p));
    return a;
}
__device__ __forceinline__ void cp16(uint32_t dst, const void* src, uint32_t sz) {
    asm volatile("cp.async.ca.shared.global [%0], [%1], 16, %2;\n" :: "r"(dst), "l"(src), "r"(sz));
}
#define CP_COMMIT() asm volatile("cp.async.commit_group;\n" ::: "memory")
template <int N>
__device__ __forceinline__ void cp_wait() {
    asm volatile("cp.async.wait_group %0;" :: "n"(N) : "memory");
}

__device__ __forceinline__ void mma16816(float* c, const uint32_t* a, const uint32_t* b) {
    asm volatile(
        "mma.sync.aligned.m16n8k16.row.col.f32.f16.f16.f32 "
        "{%0,%1,%2,%3}, {%4,%5,%6,%7}, {%8,%9}, {%0,%1,%2,%3};"
        : "+f"(c[0]), "+f"(c[1]), "+f"(c[2]), "+f"(c[3])
        : "r"(a[0]), "r"(a[1]), "r"(a[2]), "r"(a[3]), "r"(b[0]), "r"(b[1]));
}
#define LDSM4(r0, r1, r2, r3, a) \
    asm volatile("ldmatrix.sync.aligned.m8n8.x4.shared.b16 {%0,%1,%2,%3}, [%4];" \
        : "=r"(r0), "=r"(r1), "=r"(r2), "=r"(r3) : "r"(a))

// ---------------------------------------------------------------------------
// fp16 mma.sync GEMM (fp32 accum) with fused A-sources and fused epilogues.
// AMODE: 0 = direct A[m,k] (fp16)
//        1 = edge gather from ns_tf: k<256 -> src[e], k>=256 -> snk[e]
//        2 = node concat: k<256 -> inc_tf[m], k>=256 -> ns_tf[m]
// EPI:   0 = Ch[m,c] = fp16((relu?)(v + bias))
//        1 = atomicAdd(incf[b, snk[e], c], v + bias)       (fp32)
//        2 = ns[m, 2+c] += v + bias; ns_tf = fp16(new)     (c < 254)
// ---------------------------------------------------------------------------
template <int AMODE>
__device__ __forceinline__ void load_chunk(
    int c, uint32_t sb, int tid, int m0, int n0, int bIdx,
    const __half* __restrict__ A, const __half* __restrict__ Wt,
    const __half* __restrict__ nsrc, const __half* __restrict__ incsrc,
    const int* sSrc, const int* sSnk, int Ncol) {
    const int kt = c * BKh;                       // in halves
    const uint32_t abuf = sb + (uint32_t)(c % STAGES) * BUFBYTES;
    const uint32_t bbuf = abuf + ABYTES_;
    // A tile: 128 rows x 64 halves (128B rows, XOR swizzle at 16B granularity)
#pragma unroll
    for (int j = 0; j < 8; j++) {
        int idx = tid + 128 * j;                  // 0..1023
        int row = idx >> 3, c4 = idx & 7;
        uint32_t dst = abuf + (uint32_t)(row * 128 + ((c4 * 16) ^ ((row & 7) << 4)));
        const __half* src;
        if (AMODE == 0) {
            src = A + (size_t)(m0 + row) * KDIM + kt + c4 * 8;
        } else if (AMODE == 1) {
            int node = (kt < DD) ? sSrc[row] : sSnk[row];
            int cb = (kt < DD) ? kt : (kt - DD);
            src = nsrc + ((size_t)bIdx * NN + node) * DD + cb + c4 * 8;
        } else {
            size_t rg = (size_t)(m0 + row);
            src = (kt < DD) ? (incsrc + rg * DD + kt + c4 * 8)
                            : (nsrc + rg * DD + (kt - DD) + c4 * 8);
        }
        cp16(dst, src, 16);
    }
    // B tile: 128 n-rows x 64 halves, row-guarded (Ncol=254 case -> zero fill)
#pragma unroll
    for (int j = 0; j < 8; j++) {
        int idx = tid + 128 * j;                  // 0..1023
        int row = idx >> 3, c4 = idx & 7;
        uint32_t dst = bbuf + (uint32_t)(row * 128 + ((c4 * 16) ^ ((row & 7) << 4)));
        int nr = n0 + row;
        int ok = nr < Ncol;
        cp16(dst, Wt + (size_t)(ok ? nr : 0) * KDIM + kt + c4 * 8, ok ? 16u : 0u);
    }
    CP_COMMIT();
}

template <int AMODE, int EPI, int RELU>
__global__ __launch_bounds__(128, 2)
void gemm_mma(const __half* __restrict__ A, const __half* __restrict__ Wt,
              const float* __restrict__ bias, __half* __restrict__ Ch,
              float* __restrict__ incf,
              const int* __restrict__ esrc, const int* __restrict__ esnk,
              const __half* __restrict__ nsrc, const __half* __restrict__ incsrc,
              float* __restrict__ nsdst, __half* __restrict__ nstf,
              int M, int Ncol) {
    extern __shared__ __align__(16) char smem[];
    const uint32_t sb = smem_u32(smem);
    const int tid = threadIdx.x;
    const int wid = tid >> 5, lane = tid & 31;
    const int g = lane >> 2, t4 = lane & 3;
    const int wm = wid >> 1, wn = wid & 1;        // 2 x 2 warp grid
    const int m0 = blockIdx.y * TMv;
    const int n0 = blockIdx.x * TNv;
    const int bIdx = (AMODE == 1 || EPI == 1) ? (m0 / EE) : 0;
    int* sSrc = (int*)(smem + SOFF_SRC);
    int* sSnk = (int*)(smem + SOFF_SNK);

    if (AMODE == 1 || EPI == 1) {
        if (tid < TMv) {                           // blockDim=128 == TMv
            int e = (m0 - bIdx * EE) + tid;
            if (AMODE == 1) sSrc[tid] = esrc[e];
            sSnk[tid] = esnk[e];
        }
        __syncthreads();
    }

    // ldmatrix lane-constant address components
    const int sub = lane >> 3, r = lane & 7;
    const uint32_t aRowOff = (uint32_t)((wm * 64 + (sub & 1) * 8 + r) * 128);
    const uint32_t bRowOff = (uint32_t)((wn * 64 + (sub >> 1) * 8 + r) * 128);
    uint32_t aK[4], bK[4];
#pragma unroll
    for (int kk = 0; kk < 4; kk++) {
        aK[kk] = (uint32_t)((kk * 32 + (sub >> 1) * 16) ^ (r << 4));
        bK[kk] = (uint32_t)((kk * 32 + (sub & 1) * 16) ^ (r << 4));
    }

    float acc[4][8][4];
#pragma unroll
    for (int mt = 0; mt < 4; mt++)
#pragma unroll
        for (int nt = 0; nt < 8; nt++)
#pragma unroll
            for (int i = 0; i < 4; i++) acc[mt][nt][i] = 0.f;

    // Prologue: fill STAGES-1 buffers
#pragma unroll
    for (int c = 0; c < STAGES - 1; c++)
        load_chunk<AMODE>(c, sb, tid, m0, n0, bIdx, A, Wt, nsrc, incsrc, sSrc, sSnk, Ncol);

#pragma unroll 1
    for (int c = 0; c < NCHUNK; c++) {
        cp_wait<STAGES - 2>();
        __syncthreads();

        if (c + STAGES - 1 < NCHUNK)
            load_chunk<AMODE>(c + STAGES - 1, sb, tid, m0, n0, bIdx,
                              A, Wt, nsrc, incsrc, sSrc, sSnk, Ncol);

        const uint32_t abuf = sb + (uint32_t)(c % STAGES) * BUFBYTES;
        const uint32_t bbuf = abuf + ABYTES_;
#pragma unroll
        for (int kk = 0; kk < 4; kk++) {          // k16 per kk
            uint32_t a[4][4];
#pragma unroll
            for (int mt = 0; mt < 4; mt++)
                LDSM4(a[mt][0], a[mt][1], a[mt][2], a[mt][3],
                      abuf + aRowOff + (uint32_t)(mt * 2048) + aK[kk]);
            uint32_t b[8][2];
#pragma unroll
            for (int p2 = 0; p2 < 4; p2++)
                LDSM4(b[2 * p2][0], b[2 * p2][1], b[2 * p2 + 1][0], b[2 * p2 + 1][1],
                      bbuf + bRowOff + (uint32_t)(p2 * 2048) + bK[kk]);
#pragma unroll
            for (int mt = 0; mt < 4; mt++)
#pragma unroll
                for (int nt = 0; nt < 8; nt++) mma16816(acc[mt][nt], a[mt], b[nt]);
        }
    }

    // Epilogue: thread owns rows {rl0, rl0+8} x cols {cc, cc+1} per (mt, nt)
#pragma unroll
    for (int mt = 0; mt < 4; mt++) {
        const int rl0 = wm * 64 + mt * 16 + g;
#pragma unroll
        for (int nt = 0; nt < 8; nt++) {
            const int cc = n0 + wn * 64 + nt * 8 + t4 * 2;
            const float b0v = bias[cc], b1v = bias[cc + 1];
            float v0 = acc[mt][nt][0] + b0v;
            float v1 = acc[mt][nt][1] + b1v;
            float v2 = acc[mt][nt][2] + b0v;
            float v3 = acc[mt][nt][3] + b1v;
            if (RELU) {
                v0 = fmaxf(v0, 0.f); v1 = fmaxf(v1, 0.f);
                v2 = fmaxf(v2, 0.f); v3 = fmaxf(v3, 0.f);
            }
            if (EPI == 0) {
                *(__half2*)(Ch + (size_t)(m0 + rl0) * Ncol + cc) = __floats2half2_rn(v0, v1);
                *(__half2*)(Ch + (size_t)(m0 + rl0 + 8) * Ncol + cc) = __floats2half2_rn(v2, v3);
            } else if (EPI == 1) {
                float* d0 = incf + ((size_t)bIdx * NN + sSnk[rl0]) * MSGD + cc;
                float* d1 = incf + ((size_t)bIdx * NN + sSnk[rl0 + 8]) * MSGD + cc;
                atomicAdd(d0, v0); atomicAdd(d0 + 1, v1);
                atomicAdd(d1, v2); atomicAdd(d1 + 1, v3);
            } else {
                size_t r0 = (size_t)(m0 + rl0) * DD + (DD - UPDD);
                size_t r1 = (size_t)(m0 + rl0 + 8) * DD + (DD - UPDD);
                if (cc < UPDD) {
                    float u0 = nsdst[r0 + cc] + v0; nsdst[r0 + cc] = u0; nstf[r0 + cc] = __float2half_rn(u0);
                    float u2 = nsdst[r1 + cc] + v2; nsdst[r1 + cc] = u2; nstf[r1 + cc] = __float2half_rn(u2);
                }
                if (cc + 1 < UPDD) {
                    float u1 = nsdst[r0 + cc + 1] + v1; nsdst[r0 + cc + 1] = u1; nstf[r0 + cc + 1] = __float2half_rn(u1);
                    float u3 = nsdst[r1 + cc + 1] + v3; nsdst[r1 + cc + 1] = u3; nstf[r1 + cc + 1] = __float2half_rn(u3);
                }
            }
        }
    }
}

// ---------------------------------------------------------------------------
// Glue kernels
// ---------------------------------------------------------------------------
__global__ void copy_round_kernel(float4* __restrict__ dst, __half2* __restrict__ dtf,
                                  const float4* __restrict__ src, int n4) {
    int i = blockIdx.x * blockDim.x + threadIdx.x;
    if (i >= n4) return;
    float4 v = src[i];
    dst[i] = v;
    dtf[i * 2]     = __floats2half2_rn(v.x, v.y);
    dtf[i * 2 + 1] = __floats2half2_rn(v.z, v.w);
}
__global__ void round4_kernel(__half2* __restrict__ dst, const float4* __restrict__ src, int n4) {
    int i = blockIdx.x * blockDim.x + threadIdx.x;
    if (i >= n4) return;
    float4 v = src[i];
    dst[i * 2]     = __floats2half2_rn(v.x, v.y);
    dst[i * 2 + 1] = __floats2half2_rn(v.z, v.w);
}
__global__ void zero4_kernel(float4* __restrict__ dst, int n4) {
    int i = blockIdx.x * blockDim.x + threadIdx.x;
    if (i < n4) dst[i] = make_float4(0.f, 0.f, 0.f, 0.f);
}
// out[n*K+k] = fp16(in[k*N+n])
__global__ void transpose_kernel(const float* __restrict__ in, __half* __restrict__ out,
                                 int K, int N) {
    __shared__ float t[32][33];
    int k0 = blockIdx.y * 32, n0 = blockIdx.x * 32;
    int tx = threadIdx.x, ty = threadIdx.y;
    for (int i = ty; i < 32; i += 8) {
        int k = k0 + i, n = n0 + tx;
        t[i][tx] = (k < K && n < N) ? in[(size_t)k * N + n] : 0.f;
    }
    __syncthreads();
    for (int i = ty; i < 32; i += 8) {
        int n = n0 + i, k = k0 + tx;
        if (n < N && k < K) out[(size_t)n * K + k] = __float2half_rn(t[tx][i]);
    }
}

// ---------------------------------------------------------------------------
// Extraction: out[b,p,d] += sum over n-chunk of attn[b,p,n] * ns[b,n,d]  (fp32)
// ---------------------------------------------------------------------------
__global__ __launch_bounds__(256)
void extract_kernel(const float* __restrict__ attn, const float* __restrict__ ns,
                    float* __restrict__ out) {
    const int b = blockIdx.z >> 5, kc = blockIdx.z & 31;
    const float* Ab = attn + (size_t)b * PP * NN + (size_t)kc * 128;
    const float* Bb = ns + (size_t)b * NN * DD + (size_t)kc * 128 * DD
                      + (size_t)blockIdx.x * 128;
    float* Cb = out + (size_t)b * PP * DD + (size_t)blockIdx.x * 128;

    __shared__ __align__(16) float sA[8][72];
    __shared__ __align__(16) float sB[8][132];
    const int tid = threadIdx.x;
    const int tx = tid & 15, ty = tid >> 4;

    float acc[4][8];
#pragma unroll
    for (int i = 0; i < 4; i++)
#pragma unroll
        for (int j = 0; j < 8; j++) acc[i][j] = 0.f;

    for (int kt = 0; kt < 128; kt += 8) {
        {
            int p = tid >> 2, kp = (tid & 3) * 2;
            float2 v = *(const float2*)(Ab + (size_t)p * NN + kt + kp);
            sA[kp][p] = v.x; sA[kp + 1][p] = v.y;
        }
        {
            int k = tid >> 5, d4 = (tid & 31) * 4;
            *(float4*)&sB[k][d4] = *(const float4*)(Bb + (size_t)(kt + k) * DD + d4);
        }
        __syncthreads();
#pragma unroll
        for (int kk = 0; kk < 8; kk++) {
            float a[4], bb[8];
#pragma unroll
            for (int i = 0; i < 4; i++) a[i] = sA[kk][ty * 4 + i];
#pragma unroll
            for (int j = 0; j < 8; j++) bb[j] = sB[kk][tx * 8 + j];
#pragma unroll
            for (int i = 0; i < 4; i++)
#pragma unroll
                for (int j = 0; j < 8; j++) acc[i][j] += a[i] * bb[j];
        }
        __syncthreads();
    }
#pragma unroll
    for (int i = 0; i < 4; i++) {
        int p = ty * 4 + i;
#pragma unroll
        for (int j = 0; j < 8; j++)
            atomicAdd(Cb + (size_t)p * DD + tx * 8 + j, acc[i][j]);
    }
}

// ---------------------------------------------------------------------------
// Launcher
// ---------------------------------------------------------------------------
extern "C" void kernel_launch(void* const* d_in, const int* in_sizes, int n_in,
                              void* d_out, int out_size) {
    (void)in_sizes; (void)n_in;
    const float* nodes = (const float*)d_in[0];
    const float* attn  = (const float*)d_in[1];
    const float* We1   = (const float*)d_in[2];
    const float* be1   = (const float*)d_in[3];
    const float* We2   = (const float*)d_in[4];
    const float* be2   = (const float*)d_in[5];
    const float* Wn1   = (const float*)d_in[6];
    const float* bn1   = (const float*)d_in[7];
    const float* Wn2   = (const float*)d_in[8];
    const float* bn2   = (const float*)d_in[9];
    const int*   esrc  = (const int*)d_in[10];
    const int*   esnk  = (const int*)d_in[11];
    float*       out   = (float*)d_out;

    float *ns, *inc;
    __half *nstf, *he, *inctf, *hn, *wte1, *wte2, *wtn1, *wtn2;
    cudaGetSymbolAddress((void**)&ns,    g_ns);
    cudaGetSymbolAddress((void**)&nstf,  g_nstf);
    cudaGetSymbolAddress((void**)&he,    g_he);
    cudaGetSymbolAddress((void**)&inc,   g_inc);
    cudaGetSymbolAddress((void**)&inctf, g_inctf);
    cudaGetSymbolAddress((void**)&hn,    g_hn);
    cudaGetSymbolAddress((void**)&wte1,  g_wte1);
    cudaGetSymbolAddress((void**)&wte2,  g_wte2);
    cudaGetSymbolAddress((void**)&wtn1,  g_wtn1);
    cudaGetSymbolAddress((void**)&wtn2,  g_wtn2);

    cudaFuncSetAttribute(gemm_mma<1, 0, 1>, cudaFuncAttributeMaxDynamicSharedMemorySize, SMEM_BYTES);
    cudaFuncSetAttribute(gemm_mma<0, 1, 0>, cudaFuncAttributeMaxDynamicSharedMemorySize, SMEM_BYTES);
    cudaFuncSetAttribute(gemm_mma<2, 0, 1>, cudaFuncAttributeMaxDynamicSharedMemorySize, SMEM_BYTES);
    cudaFuncSetAttribute(gemm_mma<0, 2, 0>, cudaFuncAttributeMaxDynamicSharedMemorySize, SMEM_BYTES);

    const int T = 256;
    const int ME = BB * EE;  // 131072
    const int MN = BB * NN;  // 32768
    const int nInc4 = BB * NN * MSGD / 4;

    // Order chosen so early app-launch indices land on GEMMs for ncu (-s 5).
    transpose_kernel<<<dim3(HH / 32, KDIM / 32), dim3(32, 8)>>>(We1, wte1, KDIM, HH);   // 0
    {
        int n4 = BB * NN * DD / 4;
        copy_round_kernel<<<(n4 + T - 1) / T, T>>>((float4*)ns, (__half2*)nstf,
                                                   (const float4*)nodes, n4);            // 1
    }
    zero4_kernel<<<(nInc4 + T - 1) / T, T>>>((float4*)inc, nInc4);                       // 2
    // GEMM1 step0                                                                        // 3
    gemm_mma<1, 0, 1><<<dim3(HH / TNv, ME / TMv), 128, SMEM_BYTES>>>(
        nullptr, wte1, be1, he, nullptr, esrc, esnk, nstf, nullptr, nullptr, nullptr, ME, HH);
    transpose_kernel<<<dim3(MSGD / 32, KDIM / 32), dim3(32, 8)>>>(We2, wte2, HH, MSGD);  // 4
    // GEMM2 step0                                                                        // 5
    gemm_mma<0, 1, 0><<<dim3(MSGD / TNv, ME / TMv), 128, SMEM_BYTES>>>(
        he, wte2, be2, nullptr, inc, esrc, esnk, nullptr, nullptr, nullptr, nullptr, ME, MSGD);
    transpose_kernel<<<dim3(HH / 32, KDIM / 32), dim3(32, 8)>>>(Wn1, wtn1, KDIM, HH);
    round4_kernel<<<(nInc4 + T - 1) / T, T>>>((__half2*)inctf, (const float4*)inc, nInc4);
    gemm_mma<2, 0, 1><<<dim3(HH / TNv, MN / TMv), 128, SMEM_BYTES>>>(
        nullptr, wtn1, bn1, hn, nullptr, nullptr, nullptr, nstf, inctf, nullptr, nullptr, MN, HH);
    transpose_kernel<<<dim3((UPDD + 31) / 32, KDIM / 32), dim3(32, 8)>>>(Wn2, wtn2, HH, UPDD);
    gemm_mma<0, 2, 0><<<dim3((UPDD + TNv - 1) / TNv, MN / TMv), 128, SMEM_BYTES>>>(
        hn, wtn2, bn2, nullptr, nullptr, nullptr, nullptr, nullptr, nullptr, ns, nstf, MN, UPDD);

    for (int step = 1; step < STEPS; step++) {
        zero4_kernel<<<(nInc4 + T - 1) / T, T>>>((float4*)inc, nInc4);
        gemm_mma<1, 0, 1><<<dim3(HH / TNv, ME / TMv), 128, SMEM_BYTES>>>(
            nullptr, wte1, be1, he, nullptr, esrc, esnk, nstf, nullptr, nullptr, nullptr, ME, HH);
        gemm_mma<0, 1, 0><<<dim3(MSGD / TNv, ME / TMv), 128, SMEM_BYTES>>>(
            he, wte2, be2, nullptr, inc, esrc, esnk, nullptr, nullptr, nullptr, nullptr, ME, MSGD);
        round4_kernel<<<(nInc4 + T - 1) / T, T>>>((__half2*)inctf, (const float4*)inc, nInc4);
        gemm_mma<2, 0, 1><<<dim3(HH / TNv, MN / TMv), 128, SMEM_BYTES>>>(
            nullptr, wtn1, bn1, hn, nullptr, nullptr, nullptr, nstf, inctf, nullptr, nullptr, MN, HH);
        gemm_mma<0, 2, 0><<<dim3((UPDD + TNv - 1) / TNv, MN / TMv), 128, SMEM_BYTES>>>(
            hn, wtn2, bn2, nullptr, nullptr, nullptr, nullptr, nullptr, nullptr, ns, nstf, MN, UPDD);
    }

    // extraction: out[b,p,d] = sum_n attn[b,p,n] * ns[b,n,d]  (fp32, split-K + atomics)
    {
        int n4 = BB * PP * DD / 4;
        zero4_kernel<<<(n4 + T - 1) / T, T>>>((float4*)out, n4);
        extract_kernel<<<dim3(DD / 128, 1, BB * 32), 256>>>(attn, ns, out);
    }
}

// round 12
// speedup vs baseline: 1.4705x; 1.4705x over previous
#include <cuda_runtime.h>
#include <cuda_fp16.h>
#include <cstdint>

// Problem constants
#define BB   8
#define NN   4096
#define EE   16384
#define PP   64
#define DD   256
#define HH   512
#define MSGD 256
#define UPDD 254
#define STEPS 3
#define KDIM 512

// Tiling: CTA 128x256, 8 warps (2 row x 4 col), warp tile 64x64, BK=64 halves
#define TMv 128
#define TNv 256
#define BKh 64                        // k-halves per chunk (128 bytes)
#define NCHUNK (KDIM / BKh)           // 8
#define STAGES 4
#define ABYTES_ (TMv * 128)           // 16384
#define BBYTES_ (TNv * 128)           // 32768
#define BUFBYTES (ABYTES_ + BBYTES_)  // 49152
#define SOFF_SRC (STAGES * BUFBYTES)        // 196608
#define SOFF_SNK (SOFF_SRC + 512)
#define SMEM_BYTES (SOFF_SNK + 512)         // 197632

// ---------------------------------------------------------------------------
// Scratch (static device globals — no runtime allocation)
// ---------------------------------------------------------------------------
__device__ float  g_ns   [BB * NN * DD];           // fp32 node states
__device__ __half g_nstf [BB * NN * DD];           // fp16 shadow of ns
__device__ __half g_he   [(size_t)BB * EE * HH];   // fp16 edge hidden
__device__ __half g_msg  [(size_t)BB * EE * MSGD]; // fp16 messages
__device__ __half g_inctf[BB * NN * MSGD];         // fp16 incoming
__device__ __half g_hn   [BB * NN * HH];           // fp16 node hidden
__device__ __half g_wte1[HH   * KDIM];
__device__ __half g_wte2[MSGD * KDIM];
__device__ __half g_wtn1[HH   * KDIM];
__device__ __half g_wtn2[UPDD * KDIM];
// CSR over sinks (edges are batch-independent)
__device__ int g_deg [NN];
__device__ int g_off [NN + 1];
__device__ int g_fill[NN];
__device__ int g_eidx[EE];

// ---------------------------------------------------------------------------
// Helpers (portable PTX only: cp.async + ldmatrix + mma.sync fp16)
// ---------------------------------------------------------------------------
__device__ __forceinline__ uint32_t smem_u32(const void* p) {
    uint32_t a;
    asm("{ .reg .u64 t; cvta.to.shared.u64 t, %1; cvt.u32.u64 %0, t; }" : "=r"(a) : "l"(p));
    return a;
}
__device__ __forceinline__ void cp16(uint32_t dst, const void* src, uint32_t sz) {
    asm volatile("cp.async.ca.shared.global [%0], [%1], 16, %2;\n" :: "r"(dst), "l"(src), "r"(sz));
}
#define CP_COMMIT() asm volatile("cp.async.commit_group;\n" ::: "memory")
template <int N>
__device__ __forceinline__ void cp_wait() {
    asm volatile("cp.async.wait_group %0;" :: "n"(N) : "memory");
}

__device__ __forceinline__ void mma16816(float* c, const uint32_t* a, const uint32_t* b) {
    asm volatile(
        "mma.sync.aligned.m16n8k16.row.col.f32.f16.f16.f32 "
        "{%0,%1,%2,%3}, {%4,%5,%6,%7}, {%8,%9}, {%0,%1,%2,%3};"
        : "+f"(c[0]), "+f"(c[1]), "+f"(c[2]), "+f"(c[3])
        : "r"(a[0]), "r"(a[1]), "r"(a[2]), "r"(a[3]), "r"(b[0]), "r"(b[1]));
}
#define LDSM4(r0, r1, r2, r3, a) \
    asm volatile("ldmatrix.sync.aligned.m8n8.x4.shared.b16 {%0,%1,%2,%3}, [%4];" \
        : "=r"(r0), "=r"(r1), "=r"(r2), "=r"(r3) : "r"(a))

// ---------------------------------------------------------------------------
// fp16 mma.sync GEMM (fp32 accum) with fused A-sources and fused epilogues.
// AMODE: 0 = direct A[m,k] (fp16)
//        1 = edge gather from ns_tf: k<256 -> src[e], k>=256 -> snk[e]
//        2 = node concat: k<256 -> inc_tf[m], k>=256 -> ns_tf[m]
// EPI:   0 = Ch[m,c] = fp16((relu?)(v + bias))
//        2 = ns[m, 2+c] += v + bias; ns_tf = fp16(new)   (c < 254)
// ---------------------------------------------------------------------------
template <int AMODE>
__device__ __forceinline__ void load_chunk(
    int c, uint32_t sb, int tid, int m0, int n0, int bIdx,
    const __half* __restrict__ A, const __half* __restrict__ Wt,
    const __half* __restrict__ nsrc, const __half* __restrict__ incsrc,
    const int* sSrc, const int* sSnk, int Ncol) {
    const int kt = c * BKh;                       // in halves
    const uint32_t abuf = sb + (uint32_t)(c & (STAGES - 1)) * BUFBYTES;
    const uint32_t bbuf = abuf + ABYTES_;
    // A tile: 128 rows x 64 halves (128B rows, XOR swizzle at 16B granularity)
#pragma unroll
    for (int j = 0; j < 4; j++) {
        int idx = tid + 256 * j;                  // 0..1023
        int row = idx >> 3, c4 = idx & 7;
        uint32_t dst = abuf + (uint32_t)(row * 128 + ((c4 * 16) ^ ((row & 7) << 4)));
        const __half* src;
        if (AMODE == 0) {
            src = A + (size_t)(m0 + row) * KDIM + kt + c4 * 8;
        } else if (AMODE == 1) {
            int node = (kt < DD) ? sSrc[row] : sSnk[row];
            int cb = (kt < DD) ? kt : (kt - DD);
            src = nsrc + ((size_t)bIdx * NN + node) * DD + cb + c4 * 8;
        } else {
            size_t rg = (size_t)(m0 + row);
            src = (kt < DD) ? (incsrc + rg * DD + kt + c4 * 8)
                            : (nsrc + rg * DD + (kt - DD) + c4 * 8);
        }
        cp16(dst, src, 16);
    }
    // B tile: 256 n-rows x 64 halves, row-guarded (Ncol=254 case -> zero fill)
#pragma unroll
    for (int j = 0; j < 8; j++) {
        int idx = tid + 256 * j;                  // 0..2047
        int row = idx >> 3, c4 = idx & 7;
        uint32_t dst = bbuf + (uint32_t)(row * 128 + ((c4 * 16) ^ ((row & 7) << 4)));
        int nr = n0 + row;
        int ok = nr < Ncol;
        cp16(dst, Wt + (size_t)(ok ? nr : 0) * KDIM + kt + c4 * 8, ok ? 16u : 0u);
    }
    CP_COMMIT();
}

template <int AMODE, int EPI, int RELU>
__global__ __launch_bounds__(256, 1)
void gemm_mma(const __half* __restrict__ A, const __half* __restrict__ Wt,
              const float* __restrict__ bias, __half* __restrict__ Ch,
              const int* __restrict__ esrc, const int* __restrict__ esnk,
              const __half* __restrict__ nsrc, const __half* __restrict__ incsrc,
              float* __restrict__ nsdst, __half* __restrict__ nstf,
              int M, int Ncol) {
    extern __shared__ __align__(16) char smem[];
    const uint32_t sb = smem_u32(smem);
    const int tid = threadIdx.x;
    const int wid = tid >> 5, lane = tid & 31;
    const int g = lane >> 2, t4 = lane & 3;
    const int wm = wid >> 2, wn = wid & 3;        // 2 x 4 warp grid
    const int m0 = blockIdx.y * TMv;
    const int n0 = blockIdx.x * TNv;
    const int bIdx = (AMODE == 1) ? (m0 / EE) : 0;
    int* sSrc = (int*)(smem + SOFF_SRC);
    int* sSnk = (int*)(smem + SOFF_SNK);

    if (AMODE == 1) {
        if (tid < TMv) {
            int e = (m0 - bIdx * EE) + tid;
            sSrc[tid] = esrc[e];
            sSnk[tid] = esnk[e];
        }
        __syncthreads();
    }

    // ldmatrix lane-constant address components
    const int sub = lane >> 3, r = lane & 7;
    const uint32_t aRowOff = (uint32_t)((wm * 64 + (sub & 1) * 8 + r) * 128);
    const uint32_t bRowOff = (uint32_t)((wn * 64 + (sub >> 1) * 8 + r) * 128);
    uint32_t aK[4], bK[4];
#pragma unroll
    for (int kk = 0; kk < 4; kk++) {
        aK[kk] = (uint32_t)((kk * 32 + (sub >> 1) * 16) ^ (r << 4));
        bK[kk] = (uint32_t)((kk * 32 + (sub & 1) * 16) ^ (r << 4));
    }

    float acc[4][8][4];
#pragma unroll
    for (int mt = 0; mt < 4; mt++)
#pragma unroll
        for (int nt = 0; nt < 8; nt++)
#pragma unroll
            for (int i = 0; i < 4; i++) acc[mt][nt][i] = 0.f;

#pragma unroll
    for (int c = 0; c < STAGES - 1; c++)
        load_chunk<AMODE>(c, sb, tid, m0, n0, bIdx, A, Wt, nsrc, incsrc, sSrc, sSnk, Ncol);

#pragma unroll 1
    for (int c = 0; c < NCHUNK; c++) {
        cp_wait<STAGES - 2>();
        __syncthreads();

        if (c + STAGES - 1 < NCHUNK)
            load_chunk<AMODE>(c + STAGES - 1, sb, tid, m0, n0, bIdx,
                              A, Wt, nsrc, incsrc, sSrc, sSnk, Ncol);

        const uint32_t abuf = sb + (uint32_t)(c & (STAGES - 1)) * BUFBYTES;
        const uint32_t bbuf = abuf + ABYTES_;
#pragma unroll
        for (int kk = 0; kk < 4; kk++) {          // k16 per kk
            uint32_t a[4][4];
#pragma unroll
            for (int mt = 0; mt < 4; mt++)
                LDSM4(a[mt][0], a[mt][1], a[mt][2], a[mt][3],
                      abuf + aRowOff + (uint32_t)(mt * 2048) + aK[kk]);
            uint32_t b[8][2];
#pragma unroll
            for (int p2 = 0; p2 < 4; p2++)
                LDSM4(b[2 * p2][0], b[2 * p2][1], b[2 * p2 + 1][0], b[2 * p2 + 1][1],
                      bbuf + bRowOff + (uint32_t)(p2 * 2048) + bK[kk]);
#pragma unroll
            for (int mt = 0; mt < 4; mt++)
#pragma unroll
                for (int nt = 0; nt < 8; nt++) mma16816(acc[mt][nt], a[mt], b[nt]);
        }
    }

    // Epilogue: thread owns rows {rl0, rl0+8} x cols {cc, cc+1} per (mt, nt)
#pragma unroll
    for (int mt = 0; mt < 4; mt++) {
        const int rl0 = wm * 64 + mt * 16 + g;
#pragma unroll
        for (int nt = 0; nt < 8; nt++) {
            const int cc = n0 + wn * 64 + nt * 8 + t4 * 2;
            const float b0v = bias[cc], b1v = bias[cc + 1];
            float v0 = acc[mt][nt][0] + b0v;
            float v1 = acc[mt][nt][1] + b1v;
            float v2 = acc[mt][nt][2] + b0v;
            float v3 = acc[mt][nt][3] + b1v;
            if (RELU) {
                v0 = fmaxf(v0, 0.f); v1 = fmaxf(v1, 0.f);
                v2 = fmaxf(v2, 0.f); v3 = fmaxf(v3, 0.f);
            }
            if (EPI == 0) {
                *(__half2*)(Ch + (size_t)(m0 + rl0) * Ncol + cc) = __floats2half2_rn(v0, v1);
                *(__half2*)(Ch + (size_t)(m0 + rl0 + 8) * Ncol + cc) = __floats2half2_rn(v2, v3);
            } else {
                size_t r0 = (size_t)(m0 + rl0) * DD + (DD - UPDD);
                size_t r1 = (size_t)(m0 + rl0 + 8) * DD + (DD - UPDD);
                if (cc < UPDD) {
                    float u0 = nsdst[r0 + cc] + v0; nsdst[r0 + cc] = u0; nstf[r0 + cc] = __float2half_rn(u0);
                    float u2 = nsdst[r1 + cc] + v2; nsdst[r1 + cc] = u2; nstf[r1 + cc] = __float2half_rn(u2);
                }
                if (cc + 1 < UPDD) {
                    float u1 = nsdst[r0 + cc + 1] + v1; nsdst[r0 + cc + 1] = u1; nstf[r0 + cc + 1] = __float2half_rn(u1);
                    float u3 = nsdst[r1 + cc + 1] + v3; nsdst[r1 + cc + 1] = u3; nstf[r1 + cc + 1] = __float2half_rn(u3);
                }
            }
        }
    }
}

// ---------------------------------------------------------------------------
// CSR build (edges fixed; batch-independent)
// ---------------------------------------------------------------------------
__global__ void csr_zero_kernel(int* __restrict__ deg, int* __restrict__ fill) {
    int i = blockIdx.x * blockDim.x + threadIdx.x;
    if (i < NN) { deg[i] = 0; fill[i] = 0; }
}
__global__ void csr_count_kernel(const int* __restrict__ esnk, int* __restrict__ deg) {
    int e = blockIdx.x * blockDim.x + threadIdx.x;
    if (e < EE) atomicAdd(&deg[esnk[e]], 1);
}
// Exclusive scan of deg[0..NN) -> off[0..NN]; single block of 1024 threads, 4 per thread.
__global__ __launch_bounds__(1024)
void csr_scan_kernel(const int* __restrict__ deg, int* __restrict__ off) {
    __shared__ int part[1024];
    int t = threadIdx.x;
    int d0 = deg[t * 4], d1 = deg[t * 4 + 1], d2 = deg[t * 4 + 2], d3 = deg[t * 4 + 3];
    int local = d0 + d1 + d2 + d3;
    part[t] = local;
    __syncthreads();
    // Hillis-Steele inclusive scan over 1024 partials
    for (int s = 1; s < 1024; s <<= 1) {
        int v = (t >= s) ? part[t - s] : 0;
        __syncthreads();
        part[t] += v;
        __syncthreads();
    }
    int excl = part[t] - local;   // exclusive prefix for this thread's group
    off[t * 4]     = excl;
    off[t * 4 + 1] = excl + d0;
    off[t * 4 + 2] = excl + d0 + d1;
    off[t * 4 + 3] = excl + d0 + d1 + d2;
    if (t == 1023) off[NN] = part[1023];
}
__global__ void csr_fill_kernel(const int* __restrict__ esnk, const int* __restrict__ off,
                                int* __restrict__ fill, int* __restrict__ eidx) {
    int e = blockIdx.x * blockDim.x + threadIdx.x;
    if (e >= EE) return;
    int n = esnk[e];
    int pos = atomicAdd(&fill[n], 1);
    eidx[off[n] + pos] = e;
}

// ---------------------------------------------------------------------------
// Gather incoming: inctf[b,n,:] = fp16( sum over incoming edges of msgs[b,e,:] )
// 1 warp per (b, n); lane owns 8 columns.
// ---------------------------------------------------------------------------
__global__ __launch_bounds__(256)
void gather_kernel(const __half* __restrict__ msgs, const int* __restrict__ off,
                   const int* __restrict__ eidx, __half* __restrict__ inctf) {
    const int n = blockIdx.x * 8 + (threadIdx.x >> 5);
    const int b = blockIdx.y;
    const int lane = threadIdx.x & 31;
    const int s = off[n], e = off[n + 1];
    const __half* base = msgs + (size_t)b * EE * MSGD;
    float acc[8];
#pragma unroll
    for (int q = 0; q < 8; q++) acc[q] = 0.f;
    for (int j = s; j < e; j++) {
        const __half2* row = (const __half2*)(base + (size_t)eidx[j] * MSGD) + lane * 4;
#pragma unroll
        for (int q = 0; q < 4; q++) {
            float2 v = __half22float2(row[q]);
            acc[2 * q] += v.x; acc[2 * q + 1] += v.y;
        }
    }
    __half2* o = (__half2*)(inctf + ((size_t)b * NN + n) * MSGD) + lane * 4;
#pragma unroll
    for (int q = 0; q < 4; q++)
        o[q] = __floats2half2_rn(acc[2 * q], acc[2 * q + 1]);
}

// ---------------------------------------------------------------------------
// Glue kernels
// ---------------------------------------------------------------------------
__global__ void copy_round_kernel(float4* __restrict__ dst, __half2* __restrict__ dtf,
                                  const float4* __restrict__ src, int n4) {
    int i = blockIdx.x * blockDim.x + threadIdx.x;
    if (i >= n4) return;
    float4 v = src[i];
    dst[i] = v;
    dtf[i * 2]     = __floats2half2_rn(v.x, v.y);
    dtf[i * 2 + 1] = __floats2half2_rn(v.z, v.w);
}
__global__ void zero4_kernel(float4* __restrict__ dst, int n4) {
    int i = blockIdx.x * blockDim.x + threadIdx.x;
    if (i < n4) dst[i] = make_float4(0.f, 0.f, 0.f, 0.f);
}
// out[n*K+k] = fp16(in[k*N+n])
__global__ void transpose_kernel(const float* __restrict__ in, __half* __restrict__ out,
                                 int K, int N) {
    __shared__ float t[32][33];
    int k0 = blockIdx.y * 32, n0 = blockIdx.x * 32;
    int tx = threadIdx.x, ty = threadIdx.y;
    for (int i = ty; i < 32; i += 8) {
        int k = k0 + i, n = n0 + tx;
        t[i][tx] = (k < K && n < N) ? in[(size_t)k * N + n] : 0.f;
    }
    __syncthreads();
    for (int i = ty; i < 32; i += 8) {
        int n = n0 + i, k = k0 + tx;
        if (n < N && k < K) out[(size_t)n * K + k] = __float2half_rn(t[tx][i]);
    }
}

// ---------------------------------------------------------------------------
// Extraction: out[b,p,d] += sum over n-chunk of attn[b,p,n] * ns[b,n,d]  (fp32)
// ---------------------------------------------------------------------------
__global__ __launch_bounds__(256)
void extract_kernel(const float* __restrict__ attn, const float* __restrict__ ns,
                    float* __restrict__ out) {
    const int b = blockIdx.z >> 5, kc = blockIdx.z & 31;
    const float* Ab = attn + (size_t)b * PP * NN + (size_t)kc * 128;
    const float* Bb = ns + (size_t)b * NN * DD + (size_t)kc * 128 * DD
                      + (size_t)blockIdx.x * 128;
    float* Cb = out + (size_t)b * PP * DD + (size_t)blockIdx.x * 128;

    __shared__ __align__(16) float sA[8][72];
    __shared__ __align__(16) float sB[8][132];
    const int tid = threadIdx.x;
    const int tx = tid & 15, ty = tid >> 4;

    float acc[4][8];
#pragma unroll
    for (int i = 0; i < 4; i++)
#pragma unroll
        for (int j = 0; j < 8; j++) acc[i][j] = 0.f;

    for (int kt = 0; kt < 128; kt += 8) {
        {
            int p = tid >> 2, kp = (tid & 3) * 2;
            float2 v = *(const float2*)(Ab + (size_t)p * NN + kt + kp);
            sA[kp][p] = v.x; sA[kp + 1][p] = v.y;
        }
        {
            int k = tid >> 5, d4 = (tid & 31) * 4;
            *(float4*)&sB[k][d4] = *(const float4*)(Bb + (size_t)(kt + k) * DD + d4);
        }
        __syncthreads();
#pragma unroll
        for (int kk = 0; kk < 8; kk++) {
            float a[4], bb[8];
#pragma unroll
            for (int i = 0; i < 4; i++) a[i] = sA[kk][ty * 4 + i];
#pragma unroll
            for (int j = 0; j < 8; j++) bb[j] = sB[kk][tx * 8 + j];
#pragma unroll
            for (int i = 0; i < 4; i++)
#pragma unroll
                for (int j = 0; j < 8; j++) acc[i][j] += a[i] * bb[j];
        }
        __syncthreads();
    }
#pragma unroll
    for (int i = 0; i < 4; i++) {
        int p = ty * 4 + i;
#pragma unroll
        for (int j = 0; j < 8; j++)
            atomicAdd(Cb + (size_t)p * DD + tx * 8 + j, acc[i][j]);
    }
}

// ---------------------------------------------------------------------------
// Launcher
// ---------------------------------------------------------------------------
extern "C" void kernel_launch(void* const* d_in, const int* in_sizes, int n_in,
                              void* d_out, int out_size) {
    (void)in_sizes; (void)n_in;
    const float* nodes = (const float*)d_in[0];
    const float* attn  = (const float*)d_in[1];
    const float* We1   = (const float*)d_in[2];
    const float* be1   = (const float*)d_in[3];
    const float* We2   = (const float*)d_in[4];
    const float* be2   = (const float*)d_in[5];
    const float* Wn1   = (const float*)d_in[6];
    const float* bn1   = (const float*)d_in[7];
    const float* Wn2   = (const float*)d_in[8];
    const float* bn2   = (const float*)d_in[9];
    const int*   esrc  = (const int*)d_in[10];
    const int*   esnk  = (const int*)d_in[11];
    float*       out   = (float*)d_out;

    float* ns;
    __half *nstf, *he, *msg, *inctf, *hn, *wte1, *wte2, *wtn1, *wtn2;
    int *deg, *off, *fill, *eidx;
    cudaGetSymbolAddress((void**)&ns,    g_ns);
    cudaGetSymbolAddress((void**)&nstf,  g_nstf);
    cudaGetSymbolAddress((void**)&he,    g_he);
    cudaGetSymbolAddress((void**)&msg,   g_msg);
    cudaGetSymbolAddress((void**)&inctf, g_inctf);
    cudaGetSymbolAddress((void**)&hn,    g_hn);
    cudaGetSymbolAddress((void**)&wte1,  g_wte1);
    cudaGetSymbolAddress((void**)&wte2,  g_wte2);
    cudaGetSymbolAddress((void**)&wtn1,  g_wtn1);
    cudaGetSymbolAddress((void**)&wtn2,  g_wtn2);
    cudaGetSymbolAddress((void**)&deg,   g_deg);
    cudaGetSymbolAddress((void**)&off,   g_off);
    cudaGetSymbolAddress((void**)&fill,  g_fill);
    cudaGetSymbolAddress((void**)&eidx,  g_eidx);

    cudaFuncSetAttribute(gemm_mma<1, 0, 1>, cudaFuncAttributeMaxDynamicSharedMemorySize, SMEM_BYTES);
    cudaFuncSetAttribute(gemm_mma<0, 0, 0>, cudaFuncAttributeMaxDynamicSharedMemorySize, SMEM_BYTES);
    cudaFuncSetAttribute(gemm_mma<2, 0, 1>, cudaFuncAttributeMaxDynamicSharedMemorySize, SMEM_BYTES);
    cudaFuncSetAttribute(gemm_mma<0, 2, 0>, cudaFuncAttributeMaxDynamicSharedMemorySize, SMEM_BYTES);

    const int T = 256;
    const int ME = BB * EE;  // 131072
    const int MN = BB * NN;  // 32768

    // CSR build (once per call; edges fixed)
    csr_zero_kernel<<<(NN + T - 1) / T, T>>>(deg, fill);
    csr_count_kernel<<<(EE + T - 1) / T, T>>>(esnk, deg);
    csr_scan_kernel<<<1, 1024>>>(deg, off);
    csr_fill_kernel<<<(EE + T - 1) / T, T>>>(esnk, off, fill, eidx);

    // Weights -> fp16 [N,K]; ns -> fp32 + fp16 shadow
    transpose_kernel<<<dim3(HH / 32, KDIM / 32), dim3(32, 8)>>>(We1, wte1, KDIM, HH);
    transpose_kernel<<<dim3(MSGD / 32, KDIM / 32), dim3(32, 8)>>>(We2, wte2, HH, MSGD);
    transpose_kernel<<<dim3(HH / 32, KDIM / 32), dim3(32, 8)>>>(Wn1, wtn1, KDIM, HH);
    transpose_kernel<<<dim3((UPDD + 31) / 32, KDIM / 32), dim3(32, 8)>>>(Wn2, wtn2, HH, UPDD);
    {
        int n4 = BB * NN * DD / 4;
        copy_round_kernel<<<(n4 + T - 1) / T, T>>>((float4*)ns, (__half2*)nstf,
                                                   (const float4*)nodes, n4);
    }

    for (int step = 0; step < STEPS; step++) {
        // GEMM1: he = fp16(relu(gather(ns_tf) @ W_e1 + b_e1))   [131072 x 512 x 512]
        gemm_mma<1, 0, 1><<<dim3(HH / TNv, ME / TMv), 256, SMEM_BYTES>>>(
            nullptr, wte1, be1, he, esrc, esnk, nstf, nullptr, nullptr, nullptr, ME, HH);
        // GEMM2: msgs = fp16(he @ W_e2 + b_e2)                  [131072 x 512 x 256]
        gemm_mma<0, 0, 0><<<dim3(MSGD / TNv, ME / TMv), 256, SMEM_BYTES>>>(
            he, wte2, be2, msg, nullptr, nullptr, nullptr, nullptr, nullptr, nullptr, ME, MSGD);
        // incoming gather via CSR (replaces scatter atomics + zero + round)
        gather_kernel<<<dim3(NN / 8, BB), 256>>>(msg, off, eidx, inctf);
        // GEMM3: hn = fp16(relu(concat(inc_tf, ns_tf) @ W_n1 + b_n1))  [32768 x 512 x 512]
        gemm_mma<2, 0, 1><<<dim3(HH / TNv, MN / TMv), 256, SMEM_BYTES>>>(
            nullptr, wtn1, bn1, hn, nullptr, nullptr, nstf, inctf, nullptr, nullptr, MN, HH);
        // GEMM4: ns[:, 2:] += hn @ W_n2 + b_n2 ; ns_tf refresh   [32768 x 512 x 254]
        gemm_mma<0, 2, 0><<<dim3(1, MN / TMv), 256, SMEM_BYTES>>>(
            hn, wtn2, bn2, nullptr, nullptr, nullptr, nullptr, nullptr, ns, nstf, MN, UPDD);
    }

    // extraction: out[b,p,d] = sum_n attn[b,p,n] * ns[b,n,d]  (fp32, split-K + atomics)
    {
        int n4 = BB * PP * DD / 4;
        zero4_kernel<<<(n4 + T - 1) / T, T>>>((float4*)out, n4);
        extract_kernel<<<dim3(DD / 128, 1, BB * 32), 256>>>(attn, ns, out);
    }
}